// round 11
// baseline (speedup 1.0000x reference)
#include <cuda_runtime.h>
#include <math.h>

// FlexibleLogisticModel: f = sigmoid( sum_f w[f]*alpha[ord(f)]*monomial_f(x) ),
// all multiset monomials deg 0..4 in D=64 vars, lex CWR order. Never reads E.
//
// Single-phase design: each block holds the FULL operand vector in smem:
//   OPS[0..2080)      = pair products   x_a x_b   (a<=b, lex)
//   OPS[2080..47840)  = triple products x_a x_b x_c (a<=b<=c, lex)
// Element space e <-> w[65+e]:  deg2 e<2080 (op=e, sc=a2); deg3 e<47840
// (op=e, sc=a3); deg4 block i1: op = e + dl(i1), sc = a4*x[i1], i1 via
// closed-form inv_C4 (pure ALU). Per-thread: 3 coalesced LDG.128 w-chunks
// PREFETCHED before the smem build (DRAM latency hidden), then LDS+FMA.
// OPS built by pure-ALU lex walk (unrank start once, O(1)/elem). No grid
// barrier. Block sums -> atomicAdd; last block applies sigmoid + resets.

#define D 64
#define NPAIR 2080
#define N3 45760
#define N4 766480
#define ETOT 814320            // 2080 + 45760 + 766480
#define NOPS 47840             // NPAIR + N3
#define TPB 512
#define NBLK 148               // 1 CTA/SM, single wave
#define NCH 203580             // ceil((ETOT-3)/4) 4-elem chunks starting at e=3
#define CPB 1376               // ceil(NCH/NBLK)
#define PERT 94                // ceil(NOPS/TPB) build elements per thread

__device__ double   g_acc   = 0.0;
__device__ unsigned g_count = 0;

__device__ __forceinline__ int C2i(int n) { return (n >= 2) ? (n * (n - 1)) / 2 : 0; }
__device__ __forceinline__ int C3i(int n) { return (n >= 3) ? (n * (n - 1) * (n - 2)) / 6 : 0; }
__device__ __forceinline__ int C4i(int n) { return (n >= 4) ? (n * (n - 1) * (n - 2) * (n - 3)) / 24 : 0; }

__device__ __forceinline__ int inv_C2(int v) {   // smallest n with C2(n) >= v
    int n = (int)(0.5f * (1.0f + sqrtf(8.0f * (float)v + 1.0f)));
    n = (n > 3) ? n - 1 : 2;
    while (C2i(n) < v) n++;
    return n;
}
__device__ __forceinline__ int inv_C3(int v) {
    int n = (int)cbrtf(6.0f * (float)v);
    n = (n > 4) ? n - 2 : 3;
    while (C3i(n) < v) n++;
    return n;
}
__device__ __forceinline__ int inv_C4(int v) {
    int n = (int)sqrtf(sqrtf(24.0f * (float)v));
    n = (n > 5) ? n - 2 : 4;
    while (C4i(n) < v) n++;
    return n;
}

// segment of element e: scale and OPS-index delta (op = e + dl)
__device__ __forceinline__ void segOf(int e, const float* __restrict__ xs,
                                      float a2, float a3, float a4,
                                      float& sc, int& dl)
{
    if (e < NPAIR)      { sc = a2; dl = 0; }
    else if (e < NOPS)  { sc = a3; dl = 0; }
    else {
        const int rem = N4 - (e - NOPS);     // [1, N4]
        const int a   = inv_C4(rem);         // a = 67 - i1
        sc = a4 * xs[67 - a];
        dl = NPAIR + N3 - C3i(a - 1) + C4i(a) - N4 - NOPS;
    }
}

__global__ void __launch_bounds__(TPB, 1)
poly_fused_kernel(const float* __restrict__ x,
                  const float* __restrict__ w,
                  const float* __restrict__ alphas,
                  float* __restrict__ out)
{
    __shared__ float  xs[D];
    __shared__ float  al[5];
    __shared__ double warp_sums[TPB / 32];
    extern __shared__ float OPS[];           // 47840 floats = 191360 B

    const int tid  = threadIdx.x;
    const int bid  = blockIdx.x;
    const int lane = tid & 31;
    if (tid < D) xs[tid] = x[tid];
    if (tid < 5) al[tid] = alphas[tid];
    __syncthreads();

    const float a2 = al[2], a3 = al[3], a4 = al[4];

    // ---- prefetch this thread's 3 w-chunks (coalesced LDG.128, 16B aligned) ----
    float4 wv[3];
    int    e0a[3], lena[3];
    #pragma unroll
    for (int k = 0; k < 3; ++k) {
        const int lc = tid + k * TPB;
        const int c  = bid * CPB + lc;
        int len = 0, e0 = 0;
        if (lc < CPB && c < NCH) {
            e0  = 3 + (c << 2);
            len = ETOT - e0; if (len > 4) len = 4;
            if (len == 4) {
                wv[k] = *(const float4*)(w + 65 + e0);   // (65+e0)*4 % 16 == 0
            } else {                                     // single global tail chunk
                float t0 = (len > 0) ? w[65 + e0]     : 0.f;
                float t1 = (len > 1) ? w[65 + e0 + 1] : 0.f;
                float t2 = (len > 2) ? w[65 + e0 + 2] : 0.f;
                wv[k] = make_float4(t0, t1, t2, 0.f);
            }
        }
        e0a[k] = e0; lena[k] = len;
    }

    // ---- build OPS by pure-ALU lex walk (overlaps DRAM latency) ----
    {
        const int s    = tid * PERT;
        const int send = (s + PERT < NOPS) ? s + PERT : NOPS;
        if (s < NOPS) {
            int j, i3, i4;
            float m3;
            if (s < NPAIR) {                 // pair region start
                const int rem = NPAIR - s;
                const int n = inv_C2(rem);
                i3 = 65 - n;
                i4 = i3 + (C2i(n) - rem);
                j  = -1;
                m3 = xs[i3];
            } else {                          // triple region start (R8-proven)
                const int e3  = s - NPAIR;
                const int rem = N3 - e3;
                const int b   = inv_C3(rem);  // b = 66 - j
                j = 66 - b;
                const int kk  = C3i(b) - rem;
                const int remp = C2i(65 - j) - kk;
                const int n   = inv_C2(remp);
                i3 = 65 - n;
                i4 = i3 + (C2i(n) - remp);
                m3 = xs[j] * xs[i3];
            }
            for (int idx = s; idx < send; ++idx) {
                OPS[idx] = m3 * xs[i4];
                if (++i4 == D) {
                    if (++i3 == D) { j = (j < 0) ? 0 : j + 1; i3 = j; }
                    i4 = i3;
                    m3 = ((j < 0) ? 1.0f : xs[j]) * xs[i3];
                }
            }
        }
    }
    __syncthreads();

    // ---- consume: per chunk, resolve segment (ALU) then LDS+FMA ----
    double local = 0.0;
    #pragma unroll
    for (int k = 0; k < 3; ++k) {
        const int len = lena[k];
        if (len == 0) continue;
        const int e0 = e0a[k];
        float sc0, sc1; int dl0, dl1;
        segOf(e0,           xs, a2, a3, a4, sc0, dl0);
        segOf(e0 + len - 1, xs, a2, a3, a4, sc1, dl1);
        const float wa[4] = { wv[k].x, wv[k].y, wv[k].z, wv[k].w };
        if (dl0 == dl1 && sc0 == sc1) {      // uniform chunk (common case)
            float d = 0.f;
            #pragma unroll
            for (int i = 0; i < 4; ++i)
                if (i < len) d += wa[i] * OPS[e0 + i + dl0];
            local += (double)(sc0 * d);
        } else {                              // boundary chunk: per-element
            #pragma unroll
            for (int i = 0; i < 4; ++i) {
                if (i < len) {
                    float sc; int dl;
                    segOf(e0 + i, xs, a2, a3, a4, sc, dl);
                    local += (double)(sc * wa[i] * OPS[e0 + i + dl]);
                }
            }
        }
    }

    // ---- deg-0/1 + first 3 deg-2 elements (block 0, warp 0) ----
    if (bid == 0 && tid < 32) {
        float s = al[1] * (w[1 + lane] * xs[lane] + w[33 + lane] * xs[32 + lane]);
        if (lane == 0)
            s += al[0] * w[0]
               + a2 * (w[65] * OPS[0] + w[66] * OPS[1] + w[67] * OPS[2]);
        local += (double)s;
    }

    // ---- warp + block reduction (double) ----
    #pragma unroll
    for (int o = 16; o > 0; o >>= 1)
        local += __shfl_down_sync(0xffffffffu, local, o);
    if (lane == 0) warp_sums[tid >> 5] = local;
    __syncthreads();

    if (tid == 0) {
        double bs = 0.0;
        #pragma unroll
        for (int i = 0; i < TPB / 32; i++) bs += warp_sums[i];
        atomicAdd(&g_acc, bs);
        __threadfence();
        const unsigned done = atomicAdd(&g_count, 1u);
        if (done == NBLK - 1) {
            const double a = atomicAdd(&g_acc, 0.0);   // all contributions visible
            out[0] = (float)(1.0 / (1.0 + exp(-a)));
            g_acc   = 0.0;   // reset for next graph replay
            g_count = 0u;
        }
    }
}

extern "C" void kernel_launch(void* const* d_in, const int* in_sizes, int n_in,
                              void* d_out, int out_size)
{
    const float* x      = (const float*)d_in[0];
    const float* w      = (const float*)d_in[1];
    const float* alphas = (const float*)d_in[2];
    // d_in[3] = E (constant, NOT read), d_in[4] = ord_ids (NOT read)
    float* out = (float*)d_out;

    const int smem = NOPS * (int)sizeof(float);          // 191360 B
    cudaFuncSetAttribute(poly_fused_kernel,
                         cudaFuncAttributeMaxDynamicSharedMemorySize, smem);
    poly_fused_kernel<<<NBLK, TPB, smem>>>(x, w, alphas, out);
}

// round 12
// speedup vs baseline: 1.6575x; 1.6575x over previous
#include <cuda_runtime.h>
#include <math.h>

// FlexibleLogisticModel: f = sigmoid( sum_f w[f]*alpha[ord(f)]*monomial_f(x) ),
// all multiset monomials deg 0..4 in D=64 vars, lex CWR order. Never reads E.
//
// Each element e of the deg2|deg3|deg4 region (w[65+e], e in [0,814320)) pairs
// with multiplier M(e) = alpha_d * prod(xs over its index tuple). Each block
// builds ONLY its 5632-element multiplier slice in smem: one closed-form
// unrank per thread + 10-step lex walk with cached prefix product. w-loads
// (coalesced, consume-order) are issued BEFORE the build so DRAM/L2 latency
// hides behind ALU. Consume: 11 x (LDS + FMA), zero per-element metadata.
// Single kernel, no grid barrier; last block applies sigmoid + resets.

#define NPAIR 2080
#define N3    45760
#define N4    766480
#define ETOT  814320           // 2080 + 45760 + 766480
#define TPB   512
#define KPT   11
#define RPB   (TPB * KPT)      // 5632 elements per block
#define NBLK  145              // ceil(ETOT / RPB), single wave on 148 SMs

__device__ double   g_acc   = 0.0;
__device__ unsigned g_count = 0;

__device__ __forceinline__ int C2i(int n) { return (n >= 2) ? (n * (n - 1)) / 2 : 0; }
__device__ __forceinline__ int C3i(int n) { return (n >= 3) ? (n * (n - 1) * (n - 2)) / 6 : 0; }
__device__ __forceinline__ int C4i(int n) { return (n >= 4) ? (n * (n - 1) * (n - 2) * (n - 3)) / 24 : 0; }

__device__ __forceinline__ int inv_C2(int v) {   // smallest n with C2(n) >= v
    int n = (int)(0.5f * (1.0f + sqrtf(8.0f * (float)v + 1.0f)));
    n = (n > 3) ? n - 1 : 2;
    while (C2i(n) < v) n++;
    return n;
}
__device__ __forceinline__ int inv_C3(int v) {
    int n = (int)cbrtf(6.0f * (float)v);
    n = (n > 4) ? n - 2 : 3;
    while (C3i(n) < v) n++;
    return n;
}
__device__ __forceinline__ int inv_C4(int v) {
    int n = (int)sqrtf(sqrtf(24.0f * (float)v));
    n = (n > 5) ? n - 2 : 4;
    while (C4i(n) < v) n++;
    return n;
}

__global__ void __launch_bounds__(TPB, 1)
poly_fused_kernel(const float* __restrict__ x,
                  const float* __restrict__ w,
                  const float* __restrict__ alphas,
                  float* __restrict__ out)
{
    __shared__ float  xs[64];
    __shared__ float  al[5];
    __shared__ float  M[RPB];
    __shared__ double warp_sums[TPB / 32];

    const int tid  = threadIdx.x;
    const int bid  = blockIdx.x;
    const int lane = tid & 31;
    if (tid < 64) xs[tid] = x[tid];
    if (tid < 5)  al[tid] = alphas[tid];
    __syncthreads();

    const int B0 = bid * RPB;

    // ---- prefetch w in CONSUME order (coalesced; issued before the build) ----
    float wreg[KPT];
    #pragma unroll
    for (int k = 0; k < KPT; ++k) {
        const int e = B0 + tid + k * TPB;
        wreg[k] = (e < ETOT) ? w[65 + e] : 0.0f;
    }

    // ---- build M[j], j in [KPT*tid, KPT*tid+KPT): unrank once, then walk ----
    {
        int e = B0 + KPT * tid;
        int j = KPT * tid;
        int d = 2, v0 = 0, v1 = 0, v2 = 0, last = 0;
        float pre = 0.0f;

        if (e < ETOT) {
            if (e < NPAIR) {                       // pair (v0, last)
                d = 2;
                const int rem = NPAIR - e;
                const int n = inv_C2(rem);
                v0 = 65 - n; last = v0 + (C2i(n) - rem);
                pre = al[2] * xs[v0];
            } else if (e < NPAIR + N3) {           // triple (v0, v1, last)
                d = 3;
                const int rem = N3 - (e - NPAIR);
                const int b = inv_C3(rem);
                v0 = 66 - b;
                const int kk = C3i(b) - rem;
                const int remp = C2i(65 - v0) - kk;
                const int n = inv_C2(remp);
                v1 = 65 - n; last = v1 + (C2i(n) - remp);
                pre = al[3] * xs[v0] * xs[v1];
            } else {                               // quad (v0, v1, v2, last)
                d = 4;
                const int rem = N4 - (e - NPAIR - N3);
                const int a = inv_C4(rem);
                v0 = 67 - a;
                const int r1 = C4i(a) - rem;
                const int rem3 = C3i(66 - v0) - r1;
                const int b = inv_C3(rem3);
                v1 = 66 - b;
                const int kk = C3i(b) - rem3;
                const int remp = C2i(65 - v1) - kk;
                const int n = inv_C2(remp);
                v2 = 65 - n; last = v2 + (C2i(n) - remp);
                pre = al[4] * xs[v0] * xs[v1] * xs[v2];
            }
        }

        #pragma unroll
        for (int k = 0; k < KPT; ++k, ++e, ++j) {
            if (e < ETOT) {
                M[j] = pre * xs[last];
                // ---- CWR-lex advance (common path: 1 incr) ----
                if (last < 63) { ++last; }
                else if (d == 2) {
                    if (v0 < 63) { ++v0; last = v0; pre = al[2] * xs[v0]; }
                    else { d = 3; v0 = v1 = 0; last = 0;
                           pre = al[3] * xs[0] * xs[0]; }
                } else if (d == 3) {
                    if (v1 < 63)      { ++v1; last = v1; pre = al[3] * xs[v0] * xs[v1]; }
                    else if (v0 < 63) { ++v0; v1 = v0; last = v0;
                                        pre = al[3] * xs[v0] * xs[v1]; }
                    else { d = 4; v0 = v1 = v2 = 0; last = 0;
                           pre = al[4] * xs[0] * xs[0] * xs[0]; }
                } else {
                    if (v2 < 63)      { ++v2; last = v2; pre = al[4] * xs[v0] * xs[v1] * xs[v2]; }
                    else if (v1 < 63) { ++v1; v2 = v1; last = v1;
                                        pre = al[4] * xs[v0] * xs[v1] * xs[v2]; }
                    else if (v0 < 63) { ++v0; v1 = v2 = v0; last = v0;
                                        pre = al[4] * xs[v0] * xs[v1] * xs[v2]; }
                    // all-63: end of element space; loop guard handles it
                }
            } else {
                M[j] = 0.0f;     // keep OOB entries clean (0 * wreg(=0))
            }
        }
    }
    __syncthreads();

    // ---- consume: 11 x (conflict-free LDS + FMA), 4 split accumulators ----
    float acc[4] = {0.f, 0.f, 0.f, 0.f};
    #pragma unroll
    for (int k = 0; k < KPT; ++k)
        acc[k & 3] += wreg[k] * M[tid + k * TPB];
    double local = (double)((acc[0] + acc[1]) + (acc[2] + acc[3]));

    // ---- deg-0 / deg-1 (block 0, warp 0) ----
    if (bid == 0 && tid < 32) {
        float s = al[1] * (w[1 + lane] * xs[lane] + w[33 + lane] * xs[32 + lane]);
        if (lane == 0) s += al[0] * w[0];
        local += (double)s;
    }

    // ---- warp + block reduction (double) ----
    #pragma unroll
    for (int o = 16; o > 0; o >>= 1)
        local += __shfl_down_sync(0xffffffffu, local, o);
    if (lane == 0) warp_sums[tid >> 5] = local;
    __syncthreads();

    if (tid == 0) {
        double bs = 0.0;
        #pragma unroll
        for (int i = 0; i < TPB / 32; i++) bs += warp_sums[i];
        atomicAdd(&g_acc, bs);
        __threadfence();
        const unsigned done = atomicAdd(&g_count, 1u);
        if (done == NBLK - 1) {
            const double a = atomicAdd(&g_acc, 0.0);   // all contributions visible
            out[0] = (float)(1.0 / (1.0 + exp(-a)));
            g_acc   = 0.0;   // reset for next graph replay
            g_count = 0u;
        }
    }
}

extern "C" void kernel_launch(void* const* d_in, const int* in_sizes, int n_in,
                              void* d_out, int out_size)
{
    const float* x      = (const float*)d_in[0];
    const float* w      = (const float*)d_in[1];
    const float* alphas = (const float*)d_in[2];
    // d_in[3] = E (constant, NOT read), d_in[4] = ord_ids (NOT read)
    float* out = (float*)d_out;

    poly_fused_kernel<<<NBLK, TPB>>>(x, w, alphas, out);
}

// round 13
// speedup vs baseline: 1.9273x; 1.1628x over previous
#include <cuda_runtime.h>
#include <math.h>

// FlexibleLogisticModel: f = sigmoid( sum_f w[f]*alpha[ord(f)]*monomial_f(x) ),
// all multiset monomials deg 0..4 in D=64 vars, lex CWR order. Never reads E.
//
// Fully fused per-thread design: element e of the deg2|deg3|deg4 region pairs
// w[65+e] with multiplier alpha_d * prod(xs over its tuple). Thread gt owns the
// 12 contiguous elements e0=3+12*gt (16B-aligned in w): 3x LDG.128 issued
// FIRST, then one closed-form unrank + a 12-step CWR-lex walk that multiplies
// in-register (no smem M, no __syncthreads, single phase). Block sums ->
// atomicAdd; last block applies sigmoid + resets (graph-replay deterministic).

#define NPAIR 2080
#define N3    45760
#define N4    766480
#define ETOT  814320           // 2080 + 45760 + 766480
#define KPT   12
#define NCH   67860            // ceil((ETOT-3)/12)
#define TPB   256
#define NBLK  266              // ceil(NCH/TPB); <=2 CTAs/SM, co-resident

__device__ double   g_acc   = 0.0;
__device__ unsigned g_count = 0;

__device__ __forceinline__ int C2i(int n) { return (n >= 2) ? (n * (n - 1)) / 2 : 0; }
__device__ __forceinline__ int C3i(int n) { return (n >= 3) ? (n * (n - 1) * (n - 2)) / 6 : 0; }
__device__ __forceinline__ int C4i(int n) { return (n >= 4) ? (n * (n - 1) * (n - 2) * (n - 3)) / 24 : 0; }

__device__ __forceinline__ int inv_C2(int v) {   // smallest n with C2(n) >= v
    int n = (int)(0.5f * (1.0f + sqrtf(8.0f * (float)v + 1.0f)));
    n = (n > 3) ? n - 1 : 2;
    while (C2i(n) < v) n++;
    return n;
}
__device__ __forceinline__ int inv_C3(int v) {
    int n = (int)cbrtf(6.0f * (float)v);
    n = (n > 4) ? n - 2 : 3;
    while (C3i(n) < v) n++;
    return n;
}
__device__ __forceinline__ int inv_C4(int v) {
    int n = (int)sqrtf(sqrtf(24.0f * (float)v));
    n = (n > 5) ? n - 2 : 4;
    while (C4i(n) < v) n++;
    return n;
}

__global__ void __launch_bounds__(TPB, 2)
poly_fused_kernel(const float* __restrict__ x,
                  const float* __restrict__ w,
                  const float* __restrict__ alphas,
                  float* __restrict__ out)
{
    __shared__ float  xs[64];
    __shared__ float  al[5];
    __shared__ double warp_sums[TPB / 32];

    const int tid  = threadIdx.x;
    const int bid  = blockIdx.x;
    const int lane = tid & 31;
    if (tid < 64) xs[tid] = x[tid];
    if (tid < 5)  al[tid] = alphas[tid];
    __syncthreads();

    const int gt = bid * TPB + tid;
    const int e0 = 3 + KPT * gt;
    double local = 0.0;

    if (gt < NCH) {
        // ---- issue all w loads first (3x LDG.128; (65+e0) % 4 == 0) ----
        float wa[KPT];
        if (e0 + KPT <= ETOT) {
            const float4* __restrict__ wv = (const float4*)(w + 65 + e0);
            const float4 v0 = wv[0], v1 = wv[1], v2 = wv[2];
            wa[0]=v0.x; wa[1]=v0.y; wa[2]=v0.z; wa[3]=v0.w;
            wa[4]=v1.x; wa[5]=v1.y; wa[6]=v1.z; wa[7]=v1.w;
            wa[8]=v2.x; wa[9]=v2.y; wa[10]=v2.z; wa[11]=v2.w;
        } else {                                  // single partial tail thread
            #pragma unroll
            for (int k = 0; k < KPT; ++k)
                wa[k] = (e0 + k < ETOT) ? w[65 + e0 + k] : 0.0f;
        }

        // ---- unrank e0 -> (d, v0, v1, v2, last, pre) ----
        int d, v0i = 0, v1i = 0, v2i = 0, last;
        float pre;
        if (e0 < NPAIR) {                          // pair (v0, last)
            d = 2;
            const int rem = NPAIR - e0;
            const int n = inv_C2(rem);
            v0i = 65 - n; last = v0i + (C2i(n) - rem);
            pre = al[2] * xs[v0i];
        } else if (e0 < NPAIR + N3) {              // triple (v0, v1, last)
            d = 3;
            const int rem = N3 - (e0 - NPAIR);
            const int b = inv_C3(rem);
            v0i = 66 - b;
            const int kk = C3i(b) - rem;
            const int remp = C2i(65 - v0i) - kk;
            const int n = inv_C2(remp);
            v1i = 65 - n; last = v1i + (C2i(n) - remp);
            pre = al[3] * xs[v0i] * xs[v1i];
        } else {                                   // quad (v0, v1, v2, last)
            d = 4;
            const int rem = N4 - (e0 - NPAIR - N3);
            const int a = inv_C4(rem);
            v0i = 67 - a;
            const int r1 = C4i(a) - rem;
            const int rem3 = C3i(66 - v0i) - r1;
            const int b = inv_C3(rem3);
            v1i = 66 - b;
            const int kk = C3i(b) - rem3;
            const int remp = C2i(65 - v1i) - kk;
            const int n = inv_C2(remp);
            v2i = 65 - n; last = v2i + (C2i(n) - remp);
            pre = al[4] * xs[v0i] * xs[v1i] * xs[v2i];
        }

        // ---- 12-step walk fused with FMA (no smem round trip) ----
        float a0 = 0.f, a1 = 0.f, a2 = 0.f, a3 = 0.f;
        int e = e0;
        #pragma unroll
        for (int k = 0; k < KPT; ++k, ++e) {
            if (e < ETOT) {
                const float p = pre * xs[last];
                if ((k & 3) == 0) a0 += wa[k] * p;
                else if ((k & 3) == 1) a1 += wa[k] * p;
                else if ((k & 3) == 2) a2 += wa[k] * p;
                else a3 += wa[k] * p;
                // CWR-lex advance (common path: 1 incr)
                if (last < 63) { ++last; }
                else if (d == 2) {
                    if (v0i < 63) { ++v0i; last = v0i; pre = al[2] * xs[v0i]; }
                    else { d = 3; v0i = v1i = 0; last = 0;
                           pre = al[3] * xs[0] * xs[0]; }
                } else if (d == 3) {
                    if (v1i < 63)      { ++v1i; last = v1i; pre = al[3] * xs[v0i] * xs[v1i]; }
                    else if (v0i < 63) { ++v0i; v1i = v0i; last = v0i;
                                         pre = al[3] * xs[v0i] * xs[v1i]; }
                    else { d = 4; v0i = v1i = v2i = 0; last = 0;
                           pre = al[4] * xs[0] * xs[0] * xs[0]; }
                } else {
                    if (v2i < 63)      { ++v2i; last = v2i; pre = al[4] * xs[v0i] * xs[v1i] * xs[v2i]; }
                    else if (v1i < 63) { ++v1i; v2i = v1i; last = v1i;
                                         pre = al[4] * xs[v0i] * xs[v1i] * xs[v2i]; }
                    else if (v0i < 63) { ++v0i; v1i = v2i = v0i; last = v0i;
                                         pre = al[4] * xs[v0i] * xs[v1i] * xs[v2i]; }
                    // all-63: end of element space (guard handles)
                }
            }
        }
        local = (double)((a0 + a1) + (a2 + a3));
    }

    // ---- deg-0/1 + first 3 deg-2 elements (block 0, warp 0) ----
    if (bid == 0 && tid < 32) {
        float s = al[1] * (w[1 + lane] * xs[lane] + w[33 + lane] * xs[32 + lane]);
        if (lane == 0) {
            s += al[0] * w[0];
            s += al[2] * xs[0] * (w[65] * xs[0] + w[66] * xs[1] + w[67] * xs[2]);
        }
        local += (double)s;
    }

    // ---- warp + block reduction (double) ----
    #pragma unroll
    for (int o = 16; o > 0; o >>= 1)
        local += __shfl_down_sync(0xffffffffu, local, o);
    if (lane == 0) warp_sums[tid >> 5] = local;
    __syncthreads();

    if (tid == 0) {
        double bs = 0.0;
        #pragma unroll
        for (int i = 0; i < TPB / 32; i++) bs += warp_sums[i];
        atomicAdd(&g_acc, bs);
        __threadfence();
        const unsigned done = atomicAdd(&g_count, 1u);
        if (done == NBLK - 1) {
            const double a = atomicAdd(&g_acc, 0.0);   // all contributions visible
            out[0] = (float)(1.0 / (1.0 + exp(-a)));
            g_acc   = 0.0;   // reset for next graph replay
            g_count = 0u;
        }
    }
}

extern "C" void kernel_launch(void* const* d_in, const int* in_sizes, int n_in,
                              void* d_out, int out_size)
{
    const float* x      = (const float*)d_in[0];
    const float* w      = (const float*)d_in[1];
    const float* alphas = (const float*)d_in[2];
    // d_in[3] = E (constant, NOT read), d_in[4] = ord_ids (NOT read)
    float* out = (float*)d_out;

    poly_fused_kernel<<<NBLK, TPB>>>(x, w, alphas, out);
}